// round 1
// baseline (speedup 1.0000x reference)
#include <cuda_runtime.h>

// TPThird: per-sample equivariant tensor product.
// NS=48, NV=10, Z=50000.
// x1: (Z,108) = [0e:48 | 1o:10x3 | 1e:10x3]
// x2: (Z,9)   = [0e:1 | 1o:3 | 2e:5]
// weights: (Z,4344) = w00(48x48)@0, w01(48x10)@2304, w10(10x10)@2784,
//   w110(10x48)@2884, w112(10x10)@3364, w12(10x10)@3464, w20(10x10)@3564,
//   w211(10x10)@3664, w213(10x48)@3764, w22(10x10)@4244
// out: (Z,156) = [r0e:48 | r1o:30 | r1e:30 | r0o:48]

#define ZNS 48
#define ZNV 10
#define X1DIM 108
#define WNUM 4344
#define OUTDIM 156

// weight offsets
#define OW00  0
#define OW01  2304
#define OW10  2784
#define OW110 2884
#define OW112 3364
#define OW12  3464
#define OW20  3564
#define OW211 3664
#define OW213 3764
#define OW22  4244

__global__ __launch_bounds__(192, 8)
void tpthird_kernel(const float* __restrict__ x1,
                    const float* __restrict__ x2,
                    const float* __restrict__ W,
                    float* __restrict__ out)
{
    const int z = blockIdx.x;
    const int tid = threadIdx.x;

    __shared__ float s_x1[X1DIM];
    __shared__ float s_x2[9];
    __shared__ float s_d1o[ZNV], s_d1e[ZNV];
    __shared__ float s_t112[ZNV][3], s_t211[ZNV][3];
    __shared__ float s_t12[ZNV][3],  s_t22[ZNV][3];

    // --- load inputs to shared ---
    const float* x1p = x1 + (size_t)z * X1DIM;
    if (tid < X1DIM) {
        s_x1[tid] = x1p[tid];
    } else if (tid < X1DIM + 9) {
        s_x2[tid - X1DIM] = x2[(size_t)z * 9 + (tid - X1DIM)];
    }
    __syncthreads();

    // --- precompute per-u activations (10 threads) ---
    if (tid < ZNV) {
        const int u = tid;
        const float a0 = s_x1[48 + u*3 + 0];  // x1_1o[u]
        const float a1 = s_x1[48 + u*3 + 1];
        const float a2 = s_x1[48 + u*3 + 2];
        const float e0 = s_x1[78 + u*3 + 0];  // x1_1e[u]
        const float e1 = s_x1[78 + u*3 + 1];
        const float e2 = s_x1[78 + u*3 + 2];
        const float b0 = s_x2[1], b1 = s_x2[2], b2 = s_x2[3];            // x2_1o
        const float c0 = s_x2[4], c1 = s_x2[5], c2 = s_x2[6];            // x2_2e
        const float c3 = s_x2[7], c4 = s_x2[8];

        s_d1o[u] = a0*b0 + a1*b1 + a2*b2;
        s_d1e[u] = e0*b0 + e1*b1 + e2*b2;

        const float IS6 = 0.4082482904638630164f;  // 1/sqrt(6)
        // W3J111 contraction == cross product / sqrt(6)
        s_t112[u][0] = (a1*b2 - a2*b1) * IS6;
        s_t112[u][1] = (a2*b0 - a0*b2) * IS6;
        s_t112[u][2] = (a0*b1 - a1*b0) * IS6;
        s_t211[u][0] = (e1*b2 - e2*b1) * IS6;
        s_t211[u][1] = (e2*b0 - e0*b2) * IS6;
        s_t211[u][2] = (e0*b1 - e1*b0) * IS6;

        const float S10 = 0.3162277660168379332f;  // 1/sqrt(10)
        const float S30 = 0.1825741858350553712f;  // 1/sqrt(30)
        // W3J121 contraction (hand-expanded)
        s_t12[u][0] =  S10*a2*c0 - S30*a0*c2 - S10*a0*c4 + S10*a1*c1;
        s_t12[u][1] =  S10*a2*c3 + S10*a0*c1 + 2.0f*S30*a1*c2;
        s_t12[u][2] = -S30*a2*c2 + S10*a2*c4 + S10*a0*c0 + S10*a1*c3;
        s_t22[u][0] =  S10*e2*c0 - S30*e0*c2 - S10*e0*c4 + S10*e1*c1;
        s_t22[u][1] =  S10*e2*c3 + S10*e0*c1 + 2.0f*S30*e1*c2;
        s_t22[u][2] = -S30*e2*c2 + S10*e2*c4 + S10*e0*c0 + S10*e1*c3;
    }
    __syncthreads();

    const float* __restrict__ Wz = W + (size_t)z * WNUM;
    float* __restrict__ oz = out + (size_t)z * OUTDIM;
    const float x20 = s_x2[0];

    const float N0E  = 0.1313064328597226f;   // sqrt(1/58)
    const float N1O  = 0.1961161351381841f;   // sqrt(3/78)
    const float N1E  = 0.3162277660168379f;   // sqrt(1/10)
    const float N0O  = 0.3162277660168379f;   // sqrt(1/10)
    const float ISQ3 = 0.5773502691896258f;   // 1/sqrt(3)

    // Warp-aligned output ownership (no intra-warp branch divergence):
    //   warps 0-1 (tid 0..63)    -> r0e  (48 active)
    //   warp  2   (tid 64..95)   -> r1o  (30 active)
    //   warp  3   (tid 96..127)  -> r1e  (30 active)
    //   warps 4-5 (tid 128..191) -> r0o  (48 active)
    if (tid < 64) {
        if (tid < 48) {
            const int w = tid;
            float acc = 0.0f;
            #pragma unroll
            for (int u = 0; u < 48; u++)
                acc += s_x1[u] * Wz[OW00 + u*48 + w];
            acc *= x20;
            float acc2 = 0.0f;
            #pragma unroll
            for (int u = 0; u < 10; u++)
                acc2 += s_d1o[u] * Wz[OW110 + u*48 + w];
            oz[w] = N0E * (acc + ISQ3 * acc2);
        }
    } else if (tid < 96) {
        const int idx = tid - 64;
        if (idx < 30) {
            const int w = idx / 3, j = idx % 3;
            float p01 = 0.0f;
            #pragma unroll
            for (int u = 0; u < 48; u++)
                p01 += s_x1[u] * Wz[OW01 + u*10 + w];
            float a10 = 0.0f, a12 = 0.0f, a211 = 0.0f;
            #pragma unroll
            for (int u = 0; u < 10; u++) {
                a10  += s_x1[48 + u*3 + j] * Wz[OW10  + u*10 + w];
                a12  += s_t12[u][j]        * Wz[OW12  + u*10 + w];
                a211 += s_t211[u][j]       * Wz[OW211 + u*10 + w];
            }
            oz[48 + idx] = N1O * (ISQ3 * (s_x2[1 + j] * p01 + x20 * a10) + a12 + a211);
        }
    } else if (tid < 128) {
        const int idx = tid - 96;
        if (idx < 30) {
            const int w = idx / 3, k = idx % 3;
            float a112 = 0.0f, a20 = 0.0f, a22 = 0.0f;
            #pragma unroll
            for (int u = 0; u < 10; u++) {
                a112 += s_t112[u][k]       * Wz[OW112 + u*10 + w];
                a20  += s_x1[78 + u*3 + k] * Wz[OW20  + u*10 + w];
                a22  += s_t22[u][k]        * Wz[OW22  + u*10 + w];
            }
            oz[78 + idx] = N1E * (a112 + ISQ3 * x20 * a20 + a22);
        }
    } else {
        const int w = tid - 128;
        if (w < 48) {
            float acc = 0.0f;
            #pragma unroll
            for (int u = 0; u < 10; u++)
                acc += s_d1e[u] * Wz[OW213 + u*48 + w];
            oz[108 + w] = N0O * ISQ3 * acc;
        }
    }
}

extern "C" void kernel_launch(void* const* d_in, const int* in_sizes, int n_in,
                              void* d_out, int out_size)
{
    const float* x1 = (const float*)d_in[0];
    const float* x2 = (const float*)d_in[1];
    const float* W  = (const float*)d_in[2];
    float* out = (float*)d_out;

    const int Z = in_sizes[0] / X1DIM;
    tpthird_kernel<<<Z, 192>>>(x1, x2, W, out);
}

// round 2
// speedup vs baseline: 1.3081x; 1.3081x over previous
#include <cuda_runtime.h>
#include <cstdint>

// TPThird: per-sample equivariant tensor product. NS=48, NV=10, Z=50000.
// x1: (Z,108) = [0e:48 | 1o:10x3 | 1e:10x3]
// x2: (Z,9)   = [0e:1 | 1o:3 | 2e:5]
// weights: (Z,4344), out: (Z,156) = [r0e:48 | r1o:30 | r1e:30 | r0o:48]

#define X1DIM 108
#define WNUM  4344
#define OUTDIM 156

#define OW00  0
#define OW01  2304
#define OW10  2784
#define OW110 2884
#define OW112 3364
#define OW12  3464
#define OW20  3564
#define OW211 3664
#define OW213 3764
#define OW22  4244

__device__ __forceinline__ uint32_t smem_u32(const void* p) {
    return (uint32_t)__cvta_generic_to_shared(p);
}

__global__ __launch_bounds__(192, 10)
void tpthird_kernel(const float* __restrict__ x1,
                    const float* __restrict__ x2,
                    const float* __restrict__ W,
                    float* __restrict__ out)
{
    const int z = blockIdx.x;
    const int tid = threadIdx.x;

    __shared__ __align__(16) float s_W[WNUM];
    __shared__ __align__(16) float s_x1[X1DIM];
    __shared__ float s_x2[9];
    __shared__ float s_d1o[10], s_d1e[10];
    __shared__ float s_t112[10][3], s_t211[10][3];
    __shared__ float s_t12[10][3],  s_t22[10][3];
    __shared__ __align__(8) unsigned long long s_mbar;

    const uint32_t mb = smem_u32(&s_mbar);

    if (tid == 0) {
        asm volatile("mbarrier.init.shared.b64 [%0], 1;" :: "r"(mb) : "memory");
    }
    if (tid < 9) {
        s_x2[tid] = x2[(size_t)z * 9 + tid];
    }
    __syncthreads();  // mbarrier init visible before TMA targets it

    if (tid == 0) {
        const uint32_t total_bytes = WNUM * 4 + X1DIM * 4;
        asm volatile("mbarrier.arrive.expect_tx.shared.b64 _, [%0], %1;"
                     :: "r"(mb), "r"(total_bytes) : "memory");
        asm volatile("cp.async.bulk.shared::cta.global.mbarrier::complete_tx::bytes "
                     "[%0], [%1], %2, [%3];"
                     :: "r"(smem_u32(s_W)),
                        "l"(W + (size_t)z * WNUM),
                        "r"((uint32_t)(WNUM * 4)),
                        "r"(mb) : "memory");
        asm volatile("cp.async.bulk.shared::cta.global.mbarrier::complete_tx::bytes "
                     "[%0], [%1], %2, [%3];"
                     :: "r"(smem_u32(s_x1)),
                        "l"(x1 + (size_t)z * X1DIM),
                        "r"((uint32_t)(X1DIM * 4)),
                        "r"(mb) : "memory");
    }

    // All threads wait for the bulk copies (phase parity 0).
    {
        uint32_t done;
        asm volatile(
            "{\n\t"
            ".reg .pred P;\n\t"
            "WAIT_%=:\n\t"
            "mbarrier.try_wait.parity.shared.b64 P, [%1], 0;\n\t"
            "selp.b32 %0, 1, 0, P;\n\t"
            "@!P bra WAIT_%=;\n\t"
            "}"
            : "=r"(done) : "r"(mb) : "memory");
    }

    // --- per-u derived activations (10 threads) ---
    if (tid < 10) {
        const int u = tid;
        const float a0 = s_x1[48 + u*3 + 0];
        const float a1 = s_x1[48 + u*3 + 1];
        const float a2 = s_x1[48 + u*3 + 2];
        const float e0 = s_x1[78 + u*3 + 0];
        const float e1 = s_x1[78 + u*3 + 1];
        const float e2 = s_x1[78 + u*3 + 2];
        const float b0 = s_x2[1], b1 = s_x2[2], b2 = s_x2[3];
        const float c0 = s_x2[4], c1 = s_x2[5], c2 = s_x2[6];
        const float c3 = s_x2[7], c4 = s_x2[8];

        s_d1o[u] = a0*b0 + a1*b1 + a2*b2;
        s_d1e[u] = e0*b0 + e1*b1 + e2*b2;

        const float IS6 = 0.4082482904638630164f;  // 1/sqrt(6)
        s_t112[u][0] = (a1*b2 - a2*b1) * IS6;
        s_t112[u][1] = (a2*b0 - a0*b2) * IS6;
        s_t112[u][2] = (a0*b1 - a1*b0) * IS6;
        s_t211[u][0] = (e1*b2 - e2*b1) * IS6;
        s_t211[u][1] = (e2*b0 - e0*b2) * IS6;
        s_t211[u][2] = (e0*b1 - e1*b0) * IS6;

        const float S10 = 0.3162277660168379332f;  // 1/sqrt(10)
        const float S30 = 0.1825741858350553712f;  // 1/sqrt(30)
        s_t12[u][0] =  S10*a2*c0 - S30*a0*c2 - S10*a0*c4 + S10*a1*c1;
        s_t12[u][1] =  S10*a2*c3 + S10*a0*c1 + 2.0f*S30*a1*c2;
        s_t12[u][2] = -S30*a2*c2 + S10*a2*c4 + S10*a0*c0 + S10*a1*c3;
        s_t22[u][0] =  S10*e2*c0 - S30*e0*c2 - S10*e0*c4 + S10*e1*c1;
        s_t22[u][1] =  S10*e2*c3 + S10*e0*c1 + 2.0f*S30*e1*c2;
        s_t22[u][2] = -S30*e2*c2 + S10*e2*c4 + S10*e0*c0 + S10*e1*c3;
    }
    __syncthreads();

    float* __restrict__ oz = out + (size_t)z * OUTDIM;
    const float x20 = s_x2[0];

    const float N0E  = 0.1313064328597226f;   // sqrt(1/58)
    const float N1O  = 0.1961161351381841f;   // sqrt(3/78)
    const float N1E  = 0.3162277660168379f;   // sqrt(1/10)
    const float N0O  = 0.3162277660168379f;   // sqrt(1/10)
    const float ISQ3 = 0.5773502691896258f;   // 1/sqrt(3)

    // Warp-aligned output ownership:
    //   warps 0-1 -> r0e (48) | warp 2 -> r1o (30) | warp 3 -> r1e (30) | warps 4-5 -> r0o (48)
    if (tid < 64) {
        if (tid < 48) {
            const int w = tid;
            float acc = 0.0f;
            #pragma unroll
            for (int u = 0; u < 48; u++)
                acc += s_x1[u] * s_W[OW00 + u*48 + w];
            acc *= x20;
            float acc2 = 0.0f;
            #pragma unroll
            for (int u = 0; u < 10; u++)
                acc2 += s_d1o[u] * s_W[OW110 + u*48 + w];
            oz[w] = N0E * (acc + ISQ3 * acc2);
        }
    } else if (tid < 96) {
        const int idx = tid - 64;
        if (idx < 30) {
            const int w = idx / 3, j = idx % 3;
            float p01 = 0.0f;
            #pragma unroll
            for (int u = 0; u < 48; u++)
                p01 += s_x1[u] * s_W[OW01 + u*10 + w];
            float a10 = 0.0f, a12 = 0.0f, a211 = 0.0f;
            #pragma unroll
            for (int u = 0; u < 10; u++) {
                a10  += s_x1[48 + u*3 + j] * s_W[OW10  + u*10 + w];
                a12  += s_t12[u][j]        * s_W[OW12  + u*10 + w];
                a211 += s_t211[u][j]       * s_W[OW211 + u*10 + w];
            }
            oz[48 + idx] = N1O * (ISQ3 * (s_x2[1 + j] * p01 + x20 * a10) + a12 + a211);
        }
    } else if (tid < 128) {
        const int idx = tid - 96;
        if (idx < 30) {
            const int w = idx / 3, k = idx % 3;
            float a112 = 0.0f, a20 = 0.0f, a22 = 0.0f;
            #pragma unroll
            for (int u = 0; u < 10; u++) {
                a112 += s_t112[u][k]       * s_W[OW112 + u*10 + w];
                a20  += s_x1[78 + u*3 + k] * s_W[OW20  + u*10 + w];
                a22  += s_t22[u][k]        * s_W[OW22  + u*10 + w];
            }
            oz[78 + idx] = N1E * (a112 + ISQ3 * x20 * a20 + a22);
        }
    } else {
        const int w = tid - 128;
        if (w < 48) {
            float acc = 0.0f;
            #pragma unroll
            for (int u = 0; u < 10; u++)
                acc += s_d1e[u] * s_W[OW213 + u*48 + w];
            oz[108 + w] = N0O * ISQ3 * acc;
        }
    }
}

extern "C" void kernel_launch(void* const* d_in, const int* in_sizes, int n_in,
                              void* d_out, int out_size)
{
    const float* x1 = (const float*)d_in[0];
    const float* x2 = (const float*)d_in[1];
    const float* W  = (const float*)d_in[2];
    float* out = (float*)d_out;

    const int Z = in_sizes[0] / X1DIM;
    tpthird_kernel<<<Z, 192>>>(x1, x2, W, out);
}